// round 1
// baseline (speedup 1.0000x reference)
#include <cuda_runtime.h>

#define V    50000
#define E    800000
#define BB   2
#define FIN  64
#define FOUT 64
#define KK   4
#define FB   (FIN * BB)   // 128 floats per (v) row

// ---------------- device scratch (allocation-free rule: __device__ globals) ----
__device__ float g_X0[V * FB];
__device__ float g_X1[V * FB];
__device__ float g_X2[V * FB];
__device__ float g_X3[V * FB];
__device__ int   g_counts[V];
__device__ int   g_rowptr[V + 1];
__device__ int   g_cursor[V];
__device__ int   g_scol[E];
__device__ float g_sval[E];

__device__ __forceinline__ float* xsel(int k) {
    switch (k) {
        case 0: return g_X0;
        case 1: return g_X1;
        case 2: return g_X2;
        default: return g_X3;
    }
}

// ---------------- 1) layout transform: x0[v, f*2+b] = inputs[b, v, f] ---------
__global__ void transpose_kernel(const float* __restrict__ in) {
    int idx = blockIdx.x * blockDim.x + threadIdx.x;   // over V*FIN
    if (idx >= V * FIN) return;
    int v = idx >> 6;
    int f = idx & 63;
    float a = in[v * FIN + f];               // b = 0
    float c = in[V * FIN + v * FIN + f];     // b = 1
    reinterpret_cast<float2*>(g_X0)[v * FIN + f] = make_float2(a, c);
}

// ---------------- 2) CSR build ------------------------------------------------
__global__ void zero_counts_kernel() {
    int i = blockIdx.x * blockDim.x + threadIdx.x;
    if (i < V) g_counts[i] = 0;
}

__global__ void hist_kernel(const int* __restrict__ rows) {
    int e = blockIdx.x * blockDim.x + threadIdx.x;
    if (e < E) atomicAdd(&g_counts[rows[e]], 1);
}

__global__ void scan_kernel() {
    __shared__ int ssum[1024];
    int t = threadIdx.x;
    const int chunk = (V + 1023) / 1024;   // 49
    int s0 = t * chunk;
    int s1 = min(s0 + chunk, V);
    int s = 0;
    for (int i = s0; i < s1; i++) s += g_counts[i];
    ssum[t] = s;
    __syncthreads();
    if (t == 0) {
        int run = 0;
        for (int i = 0; i < 1024; i++) { int c = ssum[i]; ssum[i] = run; run += c; }
    }
    __syncthreads();
    int off = ssum[t];
    for (int i = s0; i < s1; i++) {
        g_rowptr[i] = off;
        g_cursor[i] = off;
        off += g_counts[i];
    }
    if (t == 1023) g_rowptr[V] = off;   // thread 1023's chunk is past V -> off == E
}

__global__ void scatter_kernel(const float* __restrict__ vals,
                               const int* __restrict__ rows,
                               const int* __restrict__ cols) {
    int e = blockIdx.x * blockDim.x + threadIdx.x;
    if (e >= E) return;
    int p = atomicAdd(&g_cursor[rows[e]], 1);
    g_scol[p] = cols[e];
    g_sval[p] = vals[e];
}

// ---------------- 3) CSR SpMM: y = alpha * (L @ x) + beta * prev --------------
// One warp per row; lane l owns floats [4l, 4l+4) of the 128-float row.
__global__ void spmm_csr_kernel(int ksrc, int kdst, int kprev,
                                float alpha, float beta) {
    int gtid = blockIdx.x * blockDim.x + threadIdx.x;
    int r = gtid >> 5;
    int lane = gtid & 31;
    if (r >= V) return;

    const float4* __restrict__ x4 = reinterpret_cast<const float4*>(xsel(ksrc));
    int s = g_rowptr[r];
    int e = g_rowptr[r + 1];

    float4 acc = make_float4(0.f, 0.f, 0.f, 0.f);
    for (int i = s; i < e; i++) {
        float val = __ldg(&g_sval[i]);
        int   c   = __ldg(&g_scol[i]);
        float4 xv = __ldg(&x4[c * 32 + lane]);
        acc.x = fmaf(val, xv.x, acc.x);
        acc.y = fmaf(val, xv.y, acc.y);
        acc.z = fmaf(val, xv.z, acc.z);
        acc.w = fmaf(val, xv.w, acc.w);
    }

    float4 o;
    if (beta != 0.f) {
        float4 p = reinterpret_cast<const float4*>(xsel(kprev))[r * 32 + lane];
        o.x = fmaf(beta, p.x, alpha * acc.x);
        o.y = fmaf(beta, p.y, alpha * acc.y);
        o.z = fmaf(beta, p.z, alpha * acc.z);
        o.w = fmaf(beta, p.w, alpha * acc.w);
    } else {
        o.x = alpha * acc.x; o.y = alpha * acc.y;
        o.z = alpha * acc.z; o.w = alpha * acc.w;
    }
    reinterpret_cast<float4*>(xsel(kdst))[r * 32 + lane] = o;
}

// ---------------- 4) GEMM epilogue -------------------------------------------
// out[b,v,o] = bias[o] + sum_{k,f} xs[k][v*128 + f*2 + b] * W[(f*4+k)*64 + o]
// Block tile: 32 v  x  2 b (= 64 rows)  x  64 outputs. 256 threads (8 warps).
// Warp w owns rows rho = 8w .. 8w+7 (rho -> v_local = rho>>1, b = rho&1).
// Lane l computes outputs o = l and o = l+32.
__global__ void gemm_kernel(const float* __restrict__ Wt,
                            const float* __restrict__ bias,
                            float* __restrict__ out) {
    __shared__ float Xs[32 * FB];        // 16 KB: 32 rows x 128 floats
    __shared__ float Ws[FIN * FOUT];     // 16 KB: per-k weight slice

    int tid  = threadIdx.x;
    int warp = tid >> 5;
    int lane = tid & 31;
    int v0   = blockIdx.x * 32;

    float acc0[8], acc1[8];
#pragma unroll
    for (int rr = 0; rr < 8; rr++) { acc0[rr] = 0.f; acc1[rr] = 0.f; }

    for (int k = 0; k < KK; k++) {
        __syncthreads();
        // stage weight slice: Ws[f*64 + o] = Wt[(f*4+k)*64 + o]
        const float4* Wt4 = reinterpret_cast<const float4*>(Wt);
        float4* Ws4 = reinterpret_cast<float4*>(Ws);
        for (int i = tid; i < FIN * FOUT / 4; i += 256) {
            int f  = i >> 4;       // 16 float4 per 64-float row
            int o4 = i & 15;
            Ws4[i] = Wt4[(f * 4 + k) * 16 + o4];
        }
        // stage X tile: 32 rows x 128 floats, fully coalesced
        const float4* src4 = reinterpret_cast<const float4*>(xsel(k));
        float4* Xs4 = reinterpret_cast<float4*>(Xs);
        for (int i = tid; i < 32 * 32; i += 256) {
            int v = v0 + (i >> 5);
            int c = i & 31;
            Xs4[i] = (v < V) ? src4[v * 32 + c] : make_float4(0.f, 0.f, 0.f, 0.f);
        }
        __syncthreads();

#pragma unroll 4
        for (int f = 0; f < FIN; f++) {
            float w0 = Ws[f * FOUT + lane];
            float w1 = Ws[f * FOUT + lane + 32];
#pragma unroll
            for (int rr = 0; rr < 8; rr++) {
                int rho = warp * 8 + rr;                 // warp-uniform -> LDS broadcast
                float xv = Xs[(rho >> 1) * FB + f * 2 + (rho & 1)];
                acc0[rr] = fmaf(xv, w0, acc0[rr]);
                acc1[rr] = fmaf(xv, w1, acc1[rr]);
            }
        }
    }

    float b0 = bias[lane];
    float b1 = bias[lane + 32];
#pragma unroll
    for (int rr = 0; rr < 8; rr++) {
        int rho = warp * 8 + rr;
        int v = v0 + (rho >> 1);
        int b = rho & 1;
        if (v < V) {
            out[(b * V + v) * FOUT + lane]      = acc0[rr] + b0;
            out[(b * V + v) * FOUT + lane + 32] = acc1[rr] + b1;
        }
    }
}

// ---------------- launch ------------------------------------------------------
extern "C" void kernel_launch(void* const* d_in, const int* in_sizes, int n_in,
                              void* d_out, int out_size) {
    const float* inputs   = (const float*)d_in[0];   // [B, V, FIN]
    const float* weight   = (const float*)d_in[1];   // [K, FIN, FOUT]
    const float* bias     = (const float*)d_in[2];   // [FOUT]
    const float* lap_vals = (const float*)d_in[3];   // [E]
    const int*   lap_rows = (const int*)d_in[4];     // [E]
    const int*   lap_cols = (const int*)d_in[5];     // [E]
    float*       out      = (float*)d_out;           // [B, V, FOUT]

    transpose_kernel<<<(V * FIN + 255) / 256, 256>>>(inputs);

    zero_counts_kernel<<<(V + 255) / 256, 256>>>();
    hist_kernel<<<(E + 255) / 256, 256>>>(lap_rows);
    scan_kernel<<<1, 1024>>>();
    scatter_kernel<<<(E + 255) / 256, 256>>>(lap_vals, lap_rows, lap_cols);

    const int spmm_blocks = (V * 32 + 255) / 256;
    // x1 = L x0
    spmm_csr_kernel<<<spmm_blocks, 256>>>(0, 1, 0, 1.f, 0.f);
    // x2 = 2 L x1 - x0
    spmm_csr_kernel<<<spmm_blocks, 256>>>(1, 2, 0, 2.f, -1.f);
    // x3 = 2 L x2 - x1
    spmm_csr_kernel<<<spmm_blocks, 256>>>(2, 3, 1, 2.f, -1.f);

    gemm_kernel<<<(V + 31) / 32, 256>>>(weight, bias, out);
}

// round 2
// speedup vs baseline: 1.2867x; 1.2867x over previous
#include <cuda_runtime.h>

#define V    50000
#define E    800000
#define BB   2
#define FIN  64
#define FOUT 64
#define KK   4
#define FB   (FIN * BB)   // 128 floats per (v) row
#define NB   ((V + 1023) / 1024)   // 49 scan blocks

// ---------------- device scratch (allocation-free rule: __device__ globals) ----
__device__ float g_X0[V * FB];
__device__ float g_X1[V * FB];
__device__ float g_X2[V * FB];
__device__ float g_X3[V * FB];
__device__ int   g_counts[V];
__device__ int   g_rowptr[V + 1];
__device__ int   g_cursor[V];
__device__ int   g_bsums[NB];
__device__ int   g_boffs[NB];
__device__ int   g_scol[E];
__device__ float g_sval[E];

__device__ __forceinline__ float* xsel(int k) {
    switch (k) {
        case 0: return g_X0;
        case 1: return g_X1;
        case 2: return g_X2;
        default: return g_X3;
    }
}

// ---------------- 1) layout transform: x0[v, f*2+b] = inputs[b, v, f] ---------
__global__ void transpose_kernel(const float* __restrict__ in) {
    int idx = blockIdx.x * blockDim.x + threadIdx.x;   // over V*FIN
    if (idx >= V * FIN) return;
    int v = idx >> 6;
    int f = idx & 63;
    float a = in[v * FIN + f];               // b = 0
    float c = in[V * FIN + v * FIN + f];     // b = 1
    reinterpret_cast<float2*>(g_X0)[v * FIN + f] = make_float2(a, c);
}

// ---------------- 2) CSR build ------------------------------------------------
__global__ void zero_counts_kernel() {
    int i = blockIdx.x * blockDim.x + threadIdx.x;
    if (i < V) g_counts[i] = 0;
}

__global__ void hist_kernel(const int* __restrict__ rows) {
    int e = blockIdx.x * blockDim.x + threadIdx.x;
    if (e < E) atomicAdd(&g_counts[rows[e]], 1);
}

// pass 1: per-block (1024 counts) reduction -> g_bsums
__global__ void scan_reduce_kernel() {
    __shared__ int swarp[32];
    int tid = threadIdx.x;
    int i = blockIdx.x * 1024 + tid;
    int v = (i < V) ? g_counts[i] : 0;
    // warp reduce
    for (int o = 16; o > 0; o >>= 1) v += __shfl_down_sync(0xffffffffu, v, o);
    if ((tid & 31) == 0) swarp[tid >> 5] = v;
    __syncthreads();
    if (tid < 32) {
        int s = swarp[tid];
        for (int o = 16; o > 0; o >>= 1) s += __shfl_down_sync(0xffffffffu, s, o);
        if (tid == 0) g_bsums[blockIdx.x] = s;
    }
}

// pass 2: exclusive scan of NB=49 block sums (single warp, serial: trivial size)
__global__ void scan_bsums_kernel() {
    if (threadIdx.x == 0) {
        int run = 0;
        for (int i = 0; i < NB; i++) { int c = g_bsums[i]; g_boffs[i] = run; run += c; }
        g_rowptr[V] = run;   // == E
    }
}

// pass 3: per-block exclusive scan + block offset -> rowptr & cursor
__global__ void scan_write_kernel() {
    __shared__ int s[1024];
    int tid = threadIdx.x;
    int i = blockIdx.x * 1024 + tid;
    int v = (i < V) ? g_counts[i] : 0;
    s[tid] = v;
    __syncthreads();
    // Hillis-Steele inclusive scan
#pragma unroll
    for (int o = 1; o < 1024; o <<= 1) {
        int t = (tid >= o) ? s[tid - o] : 0;
        __syncthreads();
        s[tid] += t;
        __syncthreads();
    }
    if (i < V) {
        int excl = s[tid] - v + g_boffs[blockIdx.x];
        g_rowptr[i] = excl;
        g_cursor[i] = excl;
    }
}

__global__ void scatter_kernel(const float* __restrict__ vals,
                               const int* __restrict__ rows,
                               const int* __restrict__ cols) {
    int e = blockIdx.x * blockDim.x + threadIdx.x;
    if (e >= E) return;
    int p = atomicAdd(&g_cursor[rows[e]], 1);
    g_scol[p] = cols[e];
    g_sval[p] = vals[e];
}

// ---------------- 3) CSR SpMM: y = alpha * (L @ x) + beta * prev --------------
// One warp per row; lane l owns floats [4l, 4l+4) of the 128-float row.
// 2-way unroll with independent accumulators to raise MLP against L2 latency.
__global__ void spmm_csr_kernel(int ksrc, int kdst, int kprev,
                                float alpha, float beta) {
    int gtid = blockIdx.x * blockDim.x + threadIdx.x;
    int r = gtid >> 5;
    int lane = gtid & 31;
    if (r >= V) return;

    const float4* __restrict__ x4 = reinterpret_cast<const float4*>(xsel(ksrc));
    int s = g_rowptr[r];
    int e = g_rowptr[r + 1];

    float4 acc0 = make_float4(0.f, 0.f, 0.f, 0.f);
    float4 acc1 = make_float4(0.f, 0.f, 0.f, 0.f);
    int i = s;
    for (; i + 1 < e; i += 2) {
        float v0 = __ldg(&g_sval[i]);
        float v1 = __ldg(&g_sval[i + 1]);
        int   c0 = __ldg(&g_scol[i]);
        int   c1 = __ldg(&g_scol[i + 1]);
        float4 xa = __ldg(&x4[c0 * 32 + lane]);
        float4 xb = __ldg(&x4[c1 * 32 + lane]);
        acc0.x = fmaf(v0, xa.x, acc0.x);
        acc0.y = fmaf(v0, xa.y, acc0.y);
        acc0.z = fmaf(v0, xa.z, acc0.z);
        acc0.w = fmaf(v0, xa.w, acc0.w);
        acc1.x = fmaf(v1, xb.x, acc1.x);
        acc1.y = fmaf(v1, xb.y, acc1.y);
        acc1.z = fmaf(v1, xb.z, acc1.z);
        acc1.w = fmaf(v1, xb.w, acc1.w);
    }
    if (i < e) {
        float v0 = __ldg(&g_sval[i]);
        int   c0 = __ldg(&g_scol[i]);
        float4 xa = __ldg(&x4[c0 * 32 + lane]);
        acc0.x = fmaf(v0, xa.x, acc0.x);
        acc0.y = fmaf(v0, xa.y, acc0.y);
        acc0.z = fmaf(v0, xa.z, acc0.z);
        acc0.w = fmaf(v0, xa.w, acc0.w);
    }
    acc0.x += acc1.x; acc0.y += acc1.y; acc0.z += acc1.z; acc0.w += acc1.w;

    float4 o;
    if (beta != 0.f) {
        float4 p = reinterpret_cast<const float4*>(xsel(kprev))[r * 32 + lane];
        o.x = fmaf(beta, p.x, alpha * acc0.x);
        o.y = fmaf(beta, p.y, alpha * acc0.y);
        o.z = fmaf(beta, p.z, alpha * acc0.z);
        o.w = fmaf(beta, p.w, alpha * acc0.w);
    } else {
        o.x = alpha * acc0.x; o.y = alpha * acc0.y;
        o.z = alpha * acc0.z; o.w = alpha * acc0.w;
    }
    reinterpret_cast<float4*>(xsel(kdst))[r * 32 + lane] = o;
}

// ---------------- 4) GEMM epilogue -------------------------------------------
// out[b,v,o] = bias[o] + sum_{k,f} xs[k][v*128 + f*2 + b] * W[(f*4+k)*64 + o]
__global__ void gemm_kernel(const float* __restrict__ Wt,
                            const float* __restrict__ bias,
                            float* __restrict__ out) {
    __shared__ float Xs[32 * FB];        // 16 KB: 32 rows x 128 floats
    __shared__ float Ws[FIN * FOUT];     // 16 KB: per-k weight slice

    int tid  = threadIdx.x;
    int warp = tid >> 5;
    int lane = tid & 31;
    int v0   = blockIdx.x * 32;

    float acc0[8], acc1[8];
#pragma unroll
    for (int rr = 0; rr < 8; rr++) { acc0[rr] = 0.f; acc1[rr] = 0.f; }

    for (int k = 0; k < KK; k++) {
        __syncthreads();
        const float4* Wt4 = reinterpret_cast<const float4*>(Wt);
        float4* Ws4 = reinterpret_cast<float4*>(Ws);
        for (int i = tid; i < FIN * FOUT / 4; i += 256) {
            int f  = i >> 4;
            int o4 = i & 15;
            Ws4[i] = Wt4[(f * 4 + k) * 16 + o4];
        }
        const float4* src4 = reinterpret_cast<const float4*>(xsel(k));
        float4* Xs4 = reinterpret_cast<float4*>(Xs);
        for (int i = tid; i < 32 * 32; i += 256) {
            int v = v0 + (i >> 5);
            int c = i & 31;
            Xs4[i] = (v < V) ? src4[v * 32 + c] : make_float4(0.f, 0.f, 0.f, 0.f);
        }
        __syncthreads();

#pragma unroll 4
        for (int f = 0; f < FIN; f++) {
            float w0 = Ws[f * FOUT + lane];
            float w1 = Ws[f * FOUT + lane + 32];
#pragma unroll
            for (int rr = 0; rr < 8; rr++) {
                int rho = warp * 8 + rr;                 // warp-uniform -> LDS broadcast
                float xv = Xs[(rho >> 1) * FB + f * 2 + (rho & 1)];
                acc0[rr] = fmaf(xv, w0, acc0[rr]);
                acc1[rr] = fmaf(xv, w1, acc1[rr]);
            }
        }
    }

    float b0 = bias[lane];
    float b1 = bias[lane + 32];
#pragma unroll
    for (int rr = 0; rr < 8; rr++) {
        int rho = warp * 8 + rr;
        int v = v0 + (rho >> 1);
        int b = rho & 1;
        if (v < V) {
            out[(b * V + v) * FOUT + lane]      = acc0[rr] + b0;
            out[(b * V + v) * FOUT + lane + 32] = acc1[rr] + b1;
        }
    }
}

// ---------------- launch ------------------------------------------------------
extern "C" void kernel_launch(void* const* d_in, const int* in_sizes, int n_in,
                              void* d_out, int out_size) {
    const float* inputs   = (const float*)d_in[0];   // [B, V, FIN]
    const float* weight   = (const float*)d_in[1];   // [K, FIN, FOUT]
    const float* bias     = (const float*)d_in[2];   // [FOUT]
    const float* lap_vals = (const float*)d_in[3];   // [E]
    const int*   lap_rows = (const int*)d_in[4];     // [E]
    const int*   lap_cols = (const int*)d_in[5];     // [E]
    float*       out      = (float*)d_out;           // [B, V, FOUT]

    transpose_kernel<<<(V * FIN + 255) / 256, 256>>>(inputs);

    zero_counts_kernel<<<(V + 255) / 256, 256>>>();
    hist_kernel<<<(E + 255) / 256, 256>>>(lap_rows);
    scan_reduce_kernel<<<NB, 1024>>>();
    scan_bsums_kernel<<<1, 32>>>();
    scan_write_kernel<<<NB, 1024>>>();
    scatter_kernel<<<(E + 255) / 256, 256>>>(lap_vals, lap_rows, lap_cols);

    const int spmm_blocks = (V * 32 + 255) / 256;
    // x1 = L x0
    spmm_csr_kernel<<<spmm_blocks, 256>>>(0, 1, 0, 1.f, 0.f);
    // x2 = 2 L x1 - x0
    spmm_csr_kernel<<<spmm_blocks, 256>>>(1, 2, 0, 2.f, -1.f);
    // x3 = 2 L x2 - x1
    spmm_csr_kernel<<<spmm_blocks, 256>>>(2, 3, 1, 2.f, -1.f);

    gemm_kernel<<<(V + 31) / 32, 256>>>(weight, bias, out);
}

// round 4
// speedup vs baseline: 1.3194x; 1.0254x over previous
#include <cuda_runtime.h>

#define V    50000
#define E    800000
#define BB   2
#define FIN  64
#define FOUT 64
#define KK   4
#define FB   (FIN * BB)   // 128 floats per (v) row
#define NB   ((V + 1023) / 1024)   // 49 scan blocks
#define GS   130          // Xs [f][rho] stride in floats (even -> LDS.64 aligned)

typedef unsigned long long u64;

// ---------------- device scratch (allocation-free rule: __device__ globals) ----
__device__ float g_X0[V * FB];
__device__ float g_X1[V * FB];
__device__ float g_X2[V * FB];
__device__ float g_X3[V * FB];
__device__ int   g_counts[V];      // zero-initialized; re-zeroed by scan_write
__device__ int   g_rowptr[V + 1];
__device__ int   g_cursor[V];
__device__ int   g_bsums[NB];
__device__ int   g_boffs[NB];
__device__ int   g_scol[E];
__device__ float g_sval[E];

__device__ __forceinline__ float* xsel(int k) {
    switch (k) {
        case 0: return g_X0;
        case 1: return g_X1;
        case 2: return g_X2;
        default: return g_X3;
    }
}

// ---------------- packed fp32 helpers (B300: FFMA-3reg is half-rate; f32x2 is full) ----
__device__ __forceinline__ u64 pack2(float lo, float hi) {
    u64 r; asm("mov.b64 %0, {%1, %2};" : "=l"(r) : "f"(lo), "f"(hi)); return r;
}
__device__ __forceinline__ void unpack2(u64 v, float& lo, float& hi) {
    asm("mov.b64 {%0, %1}, %2;" : "=f"(lo), "=f"(hi) : "l"(v));
}
__device__ __forceinline__ void fmaX2(u64& d, u64 a, u64 b) {
    asm("fma.rn.f32x2 %0, %1, %2, %0;" : "+l"(d) : "l"(a), "l"(b));
}

// ---------------- 1) fused front: transpose + histogram ----------------------
// blocks [0, 12500): x0[v, f*2+b] = inputs[b, v, f]
// blocks [12500, 15625): histogram of lap_rows (g_counts starts at 0)
#define TRANS_BLOCKS ((V * FIN) / 256)       // 12500
#define HIST_BLOCKS  (E / 256)               // 3125
__global__ void front_kernel(const float* __restrict__ in,
                             const int* __restrict__ rows) {
    int blk = blockIdx.x;
    if (blk < TRANS_BLOCKS) {
        int idx = blk * 256 + threadIdx.x;   // over V*FIN
        int v = idx >> 6;
        int f = idx & 63;
        float a = in[v * FIN + f];               // b = 0
        float c = in[V * FIN + v * FIN + f];     // b = 1
        reinterpret_cast<float2*>(g_X0)[v * FIN + f] = make_float2(a, c);
    } else {
        int e = (blk - TRANS_BLOCKS) * 256 + threadIdx.x;
        atomicAdd(&g_counts[rows[e]], 1);
    }
}

// ---------------- 2) CSR build: 3-pass scan ----------------------------------
__global__ void scan_reduce_kernel() {
    __shared__ int swarp[32];
    int tid = threadIdx.x;
    int i = blockIdx.x * 1024 + tid;
    int v = (i < V) ? g_counts[i] : 0;
    for (int o = 16; o > 0; o >>= 1) v += __shfl_down_sync(0xffffffffu, v, o);
    if ((tid & 31) == 0) swarp[tid >> 5] = v;
    __syncthreads();
    if (tid < 32) {
        int s = swarp[tid];
        for (int o = 16; o > 0; o >>= 1) s += __shfl_down_sync(0xffffffffu, s, o);
        if (tid == 0) g_bsums[blockIdx.x] = s;
    }
}

__global__ void scan_bsums_kernel() {
    if (threadIdx.x == 0) {
        int run = 0;
        for (int i = 0; i < NB; i++) { int c = g_bsums[i]; g_boffs[i] = run; run += c; }
        g_rowptr[V] = run;   // == E
    }
}

// per-block scan + write; also re-zeros g_counts for the next graph replay
__global__ void scan_write_kernel() {
    __shared__ int s[1024];
    int tid = threadIdx.x;
    int i = blockIdx.x * 1024 + tid;
    int v = (i < V) ? g_counts[i] : 0;
    s[tid] = v;
    __syncthreads();
#pragma unroll
    for (int o = 1; o < 1024; o <<= 1) {
        int t = (tid >= o) ? s[tid - o] : 0;
        __syncthreads();
        s[tid] += t;
        __syncthreads();
    }
    if (i < V) {
        int excl = s[tid] - v + g_boffs[blockIdx.x];
        g_rowptr[i] = excl;
        g_cursor[i] = excl;
        g_counts[i] = 0;     // restore invariant for next replay
    }
}

__global__ void scatter_kernel(const float* __restrict__ vals,
                               const int* __restrict__ rows,
                               const int* __restrict__ cols) {
    int e = blockIdx.x * blockDim.x + threadIdx.x;
    if (e >= E) return;
    int p = atomicAdd(&g_cursor[rows[e]], 1);
    g_scol[p] = cols[e];
    g_sval[p] = vals[e];
}

// ---------------- 3) CSR SpMM: y = alpha * (L @ x) + beta * prev --------------
__global__ void spmm_csr_kernel(int ksrc, int kdst, int kprev,
                                float alpha, float beta) {
    int gtid = blockIdx.x * blockDim.x + threadIdx.x;
    int r = gtid >> 5;
    int lane = gtid & 31;
    if (r >= V) return;

    const float4* __restrict__ x4 = reinterpret_cast<const float4*>(xsel(ksrc));
    int s = g_rowptr[r];
    int e = g_rowptr[r + 1];

    float4 acc0 = make_float4(0.f, 0.f, 0.f, 0.f);
    float4 acc1 = make_float4(0.f, 0.f, 0.f, 0.f);
    int i = s;
    for (; i + 1 < e; i += 2) {
        float v0 = __ldg(&g_sval[i]);
        float v1 = __ldg(&g_sval[i + 1]);
        int   c0 = __ldg(&g_scol[i]);
        int   c1 = __ldg(&g_scol[i + 1]);
        float4 xa = __ldg(&x4[c0 * 32 + lane]);
        float4 xb = __ldg(&x4[c1 * 32 + lane]);
        acc0.x = fmaf(v0, xa.x, acc0.x);
        acc0.y = fmaf(v0, xa.y, acc0.y);
        acc0.z = fmaf(v0, xa.z, acc0.z);
        acc0.w = fmaf(v0, xa.w, acc0.w);
        acc1.x = fmaf(v1, xb.x, acc1.x);
        acc1.y = fmaf(v1, xb.y, acc1.y);
        acc1.z = fmaf(v1, xb.z, acc1.z);
        acc1.w = fmaf(v1, xb.w, acc1.w);
    }
    if (i < e) {
        float v0 = __ldg(&g_sval[i]);
        int   c0 = __ldg(&g_scol[i]);
        float4 xa = __ldg(&x4[c0 * 32 + lane]);
        acc0.x = fmaf(v0, xa.x, acc0.x);
        acc0.y = fmaf(v0, xa.y, acc0.y);
        acc0.z = fmaf(v0, xa.z, acc0.z);
        acc0.w = fmaf(v0, xa.w, acc0.w);
    }
    acc0.x += acc1.x; acc0.y += acc1.y; acc0.z += acc1.z; acc0.w += acc1.w;

    float4 o;
    if (beta != 0.f) {
        float4 p = reinterpret_cast<const float4*>(xsel(kprev))[r * 32 + lane];
        o.x = fmaf(beta, p.x, alpha * acc0.x);
        o.y = fmaf(beta, p.y, alpha * acc0.y);
        o.z = fmaf(beta, p.z, alpha * acc0.z);
        o.w = fmaf(beta, p.w, alpha * acc0.w);
    } else {
        o.x = alpha * acc0.x; o.y = alpha * acc0.y;
        o.z = alpha * acc0.z; o.w = alpha * acc0.w;
    }
    reinterpret_cast<float4*>(xsel(kdst))[r * 32 + lane] = o;
}

// ---------------- 4) GEMM: out[b,v,o] = bias[o] + sum_{k,f} x_k[v,f,b]*W[f*4+k][o]
// Block: 128 rho-rows (64 v x 2 b) x 64 outputs. 256 threads = 16(ty) x 16(tx).
// Thread tile: 8 rows (ty*8..+7) x 4 cols (tx*4..+3), packed f32x2 accumulators
// (row-pairs in lo/hi lanes). X staged transposed [f][rho] in smem; W via L1.
__global__ void gemm_kernel(const float* __restrict__ Wt,
                            const float* __restrict__ bias,
                            float* __restrict__ out) {
    __shared__ float Xs[64 * GS];    // [f][rho], 33.3 KB

    int tid = threadIdx.x;
    int tx = tid & 15;               // cols o = tx*4 .. tx*4+3
    int ty = tid >> 4;               // rows rho = ty*8 .. ty*8+7
    int v0 = blockIdx.x * 64;        // 64 v per block = 128 rho rows

    u64 acc[4][4];                   // [row-pair p][col c]; lo=row 2p, hi=row 2p+1
#pragma unroll
    for (int p = 0; p < 4; p++)
#pragma unroll
        for (int c = 0; c < 4; c++) acc[p][c] = 0ULL;

    const float4* Wt4 = reinterpret_cast<const float4*>(Wt);

    for (int k = 0; k < KK; k++) {
        __syncthreads();
        // stage X tile transposed: Xs[f*GS + rho], rho = vl*2 + b, from
        // g_Xk[(v0+vl)*128 + f*2 + b]. __ldcg keeps L1 free for W.
        const float4* src4 = reinterpret_cast<const float4*>(xsel(k));
#pragma unroll
        for (int it = 0; it < 8; it++) {
            int i = tid + it * 256;          // 0..2047
            int vl = i >> 5;
            int c  = i & 31;                 // float4 index within 128-float row
            int v  = v0 + vl;
            float4 val = make_float4(0.f, 0.f, 0.f, 0.f);
            if (v < V) val = __ldcg(&src4[v * 32 + c]);
            int f0   = c * 2;                // j0 = 4c -> f = 2c, 2c+1
            int rho0 = vl * 2;
            Xs[f0 * GS + rho0]           = val.x;   // (f0,   b=0)
            Xs[f0 * GS + rho0 + 1]       = val.y;   // (f0,   b=1)
            Xs[(f0 + 1) * GS + rho0]     = val.z;   // (f0+1, b=0)
            Xs[(f0 + 1) * GS + rho0 + 1] = val.w;   // (f0+1, b=1)
        }
        __syncthreads();

#pragma unroll 8
        for (int f = 0; f < FIN; f++) {
            float4 w = __ldg(&Wt4[(f * 4 + k) * 16 + tx]);
            u64 wp0 = pack2(w.x, w.x);
            u64 wp1 = pack2(w.y, w.y);
            u64 wp2 = pack2(w.z, w.z);
            u64 wp3 = pack2(w.w, w.w);
            const u64* xrow = reinterpret_cast<const u64*>(&Xs[f * GS + ty * 8]);
#pragma unroll
            for (int p = 0; p < 4; p++) {
                u64 xp = xrow[p];            // LDS.64: rows (ty*8+2p, ty*8+2p+1)
                fmaX2(acc[p][0], xp, wp0);
                fmaX2(acc[p][1], xp, wp1);
                fmaX2(acc[p][2], xp, wp2);
                fmaX2(acc[p][3], xp, wp3);
            }
        }
    }

    // epilogue: row 2p -> b=0, row 2p+1 -> b=1, v = v0 + ty*4 + p
    float4 bv = __ldg(&reinterpret_cast<const float4*>(bias)[tx]);
    float4* out4 = reinterpret_cast<float4*>(out);
#pragma unroll
    for (int p = 0; p < 4; p++) {
        int v = v0 + ty * 4 + p;
        if (v < V) {
            float lo0, hi0, lo1, hi1, lo2, hi2, lo3, hi3;
            unpack2(acc[p][0], lo0, hi0);
            unpack2(acc[p][1], lo1, hi1);
            unpack2(acc[p][2], lo2, hi2);
            unpack2(acc[p][3], lo3, hi3);
            float4 o0 = make_float4(lo0 + bv.x, lo1 + bv.y, lo2 + bv.z, lo3 + bv.w);
            float4 o1 = make_float4(hi0 + bv.x, hi1 + bv.y, hi2 + bv.z, hi3 + bv.w);
            out4[(0 * V + v) * 16 + tx] = o0;    // b = 0
            out4[(1 * V + v) * 16 + tx] = o1;    // b = 1
        }
    }
}

// ---------------- launch ------------------------------------------------------
extern "C" void kernel_launch(void* const* d_in, const int* in_sizes, int n_in,
                              void* d_out, int out_size) {
    const float* inputs   = (const float*)d_in[0];   // [B, V, FIN]
    const float* weight   = (const float*)d_in[1];   // [K, FIN, FOUT]
    const float* bias     = (const float*)d_in[2];   // [FOUT]
    const float* lap_vals = (const float*)d_in[3];   // [E]
    const int*   lap_rows = (const int*)d_in[4];     // [E]
    const int*   lap_cols = (const int*)d_in[5];     // [E]
    float*       out      = (float*)d_out;           // [B, V, FOUT]

    front_kernel<<<TRANS_BLOCKS + HIST_BLOCKS, 256>>>(inputs, lap_rows);
    scan_reduce_kernel<<<NB, 1024>>>();
    scan_bsums_kernel<<<1, 32>>>();
    scan_write_kernel<<<NB, 1024>>>();
    scatter_kernel<<<(E + 255) / 256, 256>>>(lap_vals, lap_rows, lap_cols);

    const int spmm_blocks = (V * 32 + 255) / 256;
    spmm_csr_kernel<<<spmm_blocks, 256>>>(0, 1, 0, 1.f, 0.f);   // x1 = L x0
    spmm_csr_kernel<<<spmm_blocks, 256>>>(1, 2, 0, 2.f, -1.f);  // x2 = 2 L x1 - x0
    spmm_csr_kernel<<<spmm_blocks, 256>>>(2, 3, 1, 2.f, -1.f);  // x3 = 2 L x2 - x1

    gemm_kernel<<<(2 * V + 127) / 128, 256>>>(weight, bias, out);
}

// round 6
// speedup vs baseline: 1.4003x; 1.0613x over previous
#include <cuda_runtime.h>
#include <cuda_fp16.h>

#define V    50000
#define E    800000
#define BB   2
#define FIN  64
#define FOUT 64
#define KK   4
#define FB   (FIN * BB)   // 128 floats per (v) row
#define NB   ((V + 1023) / 1024)   // 49 scan blocks
#define GS   130          // Xs [f][rho] stride in floats (even -> LDS.64 aligned)

typedef unsigned long long u64;

// ---------------- device scratch (allocation-free rule: __device__ globals) ----
__device__ float   g_X0[V * FB];
__device__ float   g_X1[V * FB];
__device__ float   g_X2[V * FB];
__device__ float   g_X3[V * FB];
// fp16 mirrors of the gathered operands (x0, x1, x2); x3 is never gathered.
__device__ __half2 g_H0[V * FIN];    // [v*64 + f] = (x[v,f,b=0], x[v,f,b=1])
__device__ __half2 g_H1[V * FIN];
__device__ __half2 g_H2[V * FIN];
__device__ int     g_counts[V];      // zero-init; re-zeroed by scan_write
__device__ int     g_rowptr[V + 1];
__device__ int     g_cursor[V];
__device__ int     g_bsums[NB];
__device__ int     g_boffs[NB];
__device__ int2    g_edge[E];        // (col, float-bits of val) interleaved

__device__ __forceinline__ float* xsel(int k) {
    switch (k) {
        case 0: return g_X0;
        case 1: return g_X1;
        case 2: return g_X2;
        default: return g_X3;
    }
}
__device__ __forceinline__ __half2* hsel(int k) {
    switch (k) {
        case 0: return g_H0;
        case 1: return g_H1;
        default: return g_H2;
    }
}

// ---------------- packed fp32 helpers (B300: FFMA-3reg is half-rate; f32x2 is full) ----
__device__ __forceinline__ u64 pack2(float lo, float hi) {
    u64 r; asm("mov.b64 %0, {%1, %2};" : "=l"(r) : "f"(lo), "f"(hi)); return r;
}
__device__ __forceinline__ void unpack2(u64 v, float& lo, float& hi) {
    asm("mov.b64 {%0, %1}, %2;" : "=f"(lo), "=f"(hi) : "l"(v));
}
__device__ __forceinline__ void fmaX2(u64& d, u64 a, u64 b) {
    asm("fma.rn.f32x2 %0, %1, %2, %0;" : "+l"(d) : "l"(a), "l"(b));
}

// ---------------- 1) fused front: transpose (+fp16 mirror) + histogram -------
#define TRANS_BLOCKS ((V * FIN) / 256)       // 12500
#define HIST_BLOCKS  (E / 256)               // 3125
__global__ void front_kernel(const float* __restrict__ in,
                             const int* __restrict__ rows) {
    int blk = blockIdx.x;
    if (blk < TRANS_BLOCKS) {
        int idx = blk * 256 + threadIdx.x;   // over V*FIN
        int v = idx >> 6;
        int f = idx & 63;
        float a = in[v * FIN + f];               // b = 0
        float c = in[V * FIN + v * FIN + f];     // b = 1
        reinterpret_cast<float2*>(g_X0)[v * FIN + f] = make_float2(a, c);
        g_H0[v * FIN + f] = __floats2half2_rn(a, c);
    } else {
        int e = (blk - TRANS_BLOCKS) * 256 + threadIdx.x;
        atomicAdd(&g_counts[rows[e]], 1);
    }
}

// ---------------- 2) CSR build: 3-pass scan ----------------------------------
__global__ void scan_reduce_kernel() {
    __shared__ int swarp[32];
    int tid = threadIdx.x;
    int i = blockIdx.x * 1024 + tid;
    int v = (i < V) ? g_counts[i] : 0;
    for (int o = 16; o > 0; o >>= 1) v += __shfl_down_sync(0xffffffffu, v, o);
    if ((tid & 31) == 0) swarp[tid >> 5] = v;
    __syncthreads();
    if (tid < 32) {
        int s = swarp[tid];
        for (int o = 16; o > 0; o >>= 1) s += __shfl_down_sync(0xffffffffu, s, o);
        if (tid == 0) g_bsums[blockIdx.x] = s;
    }
}

__global__ void scan_bsums_kernel() {
    if (threadIdx.x == 0) {
        int run = 0;
        for (int i = 0; i < NB; i++) { int c = g_bsums[i]; g_boffs[i] = run; run += c; }
        g_rowptr[V] = run;   // == E
    }
}

__global__ void scan_write_kernel() {
    __shared__ int s[1024];
    int tid = threadIdx.x;
    int i = blockIdx.x * 1024 + tid;
    int v = (i < V) ? g_counts[i] : 0;
    s[tid] = v;
    __syncthreads();
#pragma unroll
    for (int o = 1; o < 1024; o <<= 1) {
        int t = (tid >= o) ? s[tid - o] : 0;
        __syncthreads();
        s[tid] += t;
        __syncthreads();
    }
    if (i < V) {
        int excl = s[tid] - v + g_boffs[blockIdx.x];
        g_rowptr[i] = excl;
        g_cursor[i] = excl;
        g_counts[i] = 0;     // restore invariant for next replay
    }
}

__global__ void scatter_kernel(const float* __restrict__ vals,
                               const int* __restrict__ rows,
                               const int* __restrict__ cols) {
    int e = blockIdx.x * blockDim.x + threadIdx.x;
    if (e >= E) return;
    int p = atomicAdd(&g_cursor[rows[e]], 1);
    g_edge[p] = make_int2(cols[e], __float_as_int(vals[e]));
}

// ---------------- 3) CSR SpMM: y = alpha * (L @ xh) + beta * prev -------------
// One warp per row. Gather operand is the fp16 mirror (256 B/row -> halves LTS
// traffic). Lane l owns floats [4l, 4l+4) == half2 pair (2l, 2l+1) == one uint2.
// Accumulation, prev, and the f32 output stay fp32; dst also writes its own
// fp16 mirror when it will be gathered by a later SpMM.
__global__ void spmm_csr_kernel(int ksrc, int kdst, int kprev,
                                float alpha, float beta, int write_mirror) {
    int gtid = blockIdx.x * blockDim.x + threadIdx.x;
    int r = gtid >> 5;
    int lane = gtid & 31;
    if (r >= V) return;

    const uint2* __restrict__ hx = reinterpret_cast<const uint2*>(hsel(ksrc));
    int s = g_rowptr[r];
    int e = g_rowptr[r + 1];

    float4 acc0 = make_float4(0.f, 0.f, 0.f, 0.f);
    float4 acc1 = make_float4(0.f, 0.f, 0.f, 0.f);
    int i = s;
    for (; i + 1 < e; i += 2) {
        int2 e0 = __ldg(&g_edge[i]);
        int2 e1 = __ldg(&g_edge[i + 1]);
        float v0 = __int_as_float(e0.y);
        float v1 = __int_as_float(e1.y);
        uint2 ra = __ldg(&hx[e0.x * 32 + lane]);
        uint2 rb = __ldg(&hx[e1.x * 32 + lane]);
        float2 a0 = __half22float2(*reinterpret_cast<__half2*>(&ra.x));
        float2 a1 = __half22float2(*reinterpret_cast<__half2*>(&ra.y));
        float2 b0 = __half22float2(*reinterpret_cast<__half2*>(&rb.x));
        float2 b1 = __half22float2(*reinterpret_cast<__half2*>(&rb.y));
        acc0.x = fmaf(v0, a0.x, acc0.x);
        acc0.y = fmaf(v0, a0.y, acc0.y);
        acc0.z = fmaf(v0, a1.x, acc0.z);
        acc0.w = fmaf(v0, a1.y, acc0.w);
        acc1.x = fmaf(v1, b0.x, acc1.x);
        acc1.y = fmaf(v1, b0.y, acc1.y);
        acc1.z = fmaf(v1, b1.x, acc1.z);
        acc1.w = fmaf(v1, b1.y, acc1.w);
    }
    if (i < e) {
        int2 e0 = __ldg(&g_edge[i]);
        float v0 = __int_as_float(e0.y);
        uint2 ra = __ldg(&hx[e0.x * 32 + lane]);
        float2 a0 = __half22float2(*reinterpret_cast<__half2*>(&ra.x));
        float2 a1 = __half22float2(*reinterpret_cast<__half2*>(&ra.y));
        acc0.x = fmaf(v0, a0.x, acc0.x);
        acc0.y = fmaf(v0, a0.y, acc0.y);
        acc0.z = fmaf(v0, a1.x, acc0.z);
        acc0.w = fmaf(v0, a1.y, acc0.w);
    }
    acc0.x += acc1.x; acc0.y += acc1.y; acc0.z += acc1.z; acc0.w += acc1.w;

    float4 o;
    if (beta != 0.f) {
        float4 p = reinterpret_cast<const float4*>(xsel(kprev))[r * 32 + lane];
        o.x = fmaf(beta, p.x, alpha * acc0.x);
        o.y = fmaf(beta, p.y, alpha * acc0.y);
        o.z = fmaf(beta, p.z, alpha * acc0.z);
        o.w = fmaf(beta, p.w, alpha * acc0.w);
    } else {
        o.x = alpha * acc0.x; o.y = alpha * acc0.y;
        o.z = alpha * acc0.z; o.w = alpha * acc0.w;
    }
    reinterpret_cast<float4*>(xsel(kdst))[r * 32 + lane] = o;

    if (write_mirror) {
        uint2 m;
        __half2 m0 = __floats2half2_rn(o.x, o.y);
        __half2 m1 = __floats2half2_rn(o.z, o.w);
        m.x = *reinterpret_cast<unsigned*>(&m0);
        m.y = *reinterpret_cast<unsigned*>(&m1);
        reinterpret_cast<uint2*>(hsel(kdst))[r * 32 + lane] = m;
    }
}

// ---------------- 4) GEMM: out[b,v,o] = bias[o] + sum_{k,f} x_k[v,f,b]*W[f*4+k][o]
__global__ void gemm_kernel(const float* __restrict__ Wt,
                            const float* __restrict__ bias,
                            float* __restrict__ out) {
    __shared__ float Xs[64 * GS];    // [f][rho], 33.3 KB

    int tid = threadIdx.x;
    int tx = tid & 15;               // cols o = tx*4 .. tx*4+3
    int ty = tid >> 4;               // rows rho = ty*8 .. ty*8+7
    int v0 = blockIdx.x * 64;        // 64 v per block = 128 rho rows

    u64 acc[4][4];
#pragma unroll
    for (int p = 0; p < 4; p++)
#pragma unroll
        for (int c = 0; c < 4; c++) acc[p][c] = 0ULL;

    const float4* Wt4 = reinterpret_cast<const float4*>(Wt);

    for (int k = 0; k < KK; k++) {
        __syncthreads();
        const float4* src4 = reinterpret_cast<const float4*>(xsel(k));
#pragma unroll
        for (int it = 0; it < 8; it++) {
            int i = tid + it * 256;          // 0..2047
            int vl = i >> 5;
            int c  = i & 31;
            int v  = v0 + vl;
            float4 val = make_float4(0.f, 0.f, 0.f, 0.f);
            if (v < V) val = __ldcg(&src4[v * 32 + c]);
            int f0   = c * 2;
            int rho0 = vl * 2;
            Xs[f0 * GS + rho0]           = val.x;
            Xs[f0 * GS + rho0 + 1]       = val.y;
            Xs[(f0 + 1) * GS + rho0]     = val.z;
            Xs[(f0 + 1) * GS + rho0 + 1] = val.w;
        }
        __syncthreads();

#pragma unroll 8
        for (int f = 0; f < FIN; f++) {
            float4 w = __ldg(&Wt4[(f * 4 + k) * 16 + tx]);
            u64 wp0 = pack2(w.x, w.x);
            u64 wp1 = pack2(w.y, w.y);
            u64 wp2 = pack2(w.z, w.z);
            u64 wp3 = pack2(w.w, w.w);
            const u64* xrow = reinterpret_cast<const u64*>(&Xs[f * GS + ty * 8]);
#pragma unroll
            for (int p = 0; p < 4; p++) {
                u64 xp = xrow[p];
                fmaX2(acc[p][0], xp, wp0);
                fmaX2(acc[p][1], xp, wp1);
                fmaX2(acc[p][2], xp, wp2);
                fmaX2(acc[p][3], xp, wp3);
            }
        }
    }

    float4 bv = __ldg(&reinterpret_cast<const float4*>(bias)[tx]);
    float4* out4 = reinterpret_cast<float4*>(out);
#pragma unroll
    for (int p = 0; p < 4; p++) {
        int v = v0 + ty * 4 + p;
        if (v < V) {
            float lo0, hi0, lo1, hi1, lo2, hi2, lo3, hi3;
            unpack2(acc[p][0], lo0, hi0);
            unpack2(acc[p][1], lo1, hi1);
            unpack2(acc[p][2], lo2, hi2);
            unpack2(acc[p][3], lo3, hi3);
            float4 o0 = make_float4(lo0 + bv.x, lo1 + bv.y, lo2 + bv.z, lo3 + bv.w);
            float4 o1 = make_float4(hi0 + bv.x, hi1 + bv.y, hi2 + bv.z, hi3 + bv.w);
            out4[(0 * V + v) * 16 + tx] = o0;    // b = 0
            out4[(1 * V + v) * 16 + tx] = o1;    // b = 1
        }
    }
}

// ---------------- launch ------------------------------------------------------
extern "C" void kernel_launch(void* const* d_in, const int* in_sizes, int n_in,
                              void* d_out, int out_size) {
    const float* inputs   = (const float*)d_in[0];   // [B, V, FIN]
    const float* weight   = (const float*)d_in[1];   // [K, FIN, FOUT]
    const float* bias     = (const float*)d_in[2];   // [FOUT]
    const float* lap_vals = (const float*)d_in[3];   // [E]
    const int*   lap_rows = (const int*)d_in[4];     // [E]
    const int*   lap_cols = (const int*)d_in[5];     // [E]
    float*       out      = (float*)d_out;           // [B, V, FOUT]

    front_kernel<<<TRANS_BLOCKS + HIST_BLOCKS, 256>>>(inputs, lap_rows);
    scan_reduce_kernel<<<NB, 1024>>>();
    scan_bsums_kernel<<<1, 32>>>();
    scan_write_kernel<<<NB, 1024>>>();
    scatter_kernel<<<(E + 255) / 256, 256>>>(lap_vals, lap_rows, lap_cols);

    const int spmm_blocks = (V * 32 + 255) / 256;
    spmm_csr_kernel<<<spmm_blocks, 256>>>(0, 1, 0, 1.f, 0.f, 1);   // x1 = L x0  (+mirror)
    spmm_csr_kernel<<<spmm_blocks, 256>>>(1, 2, 0, 2.f, -1.f, 1);  // x2 = 2Lx1 - x0 (+mirror)
    spmm_csr_kernel<<<spmm_blocks, 256>>>(2, 3, 1, 2.f, -1.f, 0);  // x3 = 2Lx2 - x1

    gemm_kernel<<<(2 * V + 127) / 128, 256>>>(weight, bias, out);
}

// round 7
// speedup vs baseline: 1.9798x; 1.4139x over previous
#include <cuda_runtime.h>
#include <cuda_fp16.h>
#include <mma.h>

using namespace nvcuda;

#define V    50000
#define E    800000
#define BB   2
#define FIN  64
#define FOUT 64
#define KK   4
#define FB   (FIN * BB)            // 128 floats per v-row (f32 buffers)
#define NB   ((V + 1023) / 1024)   // 49 scan blocks

// ---------------- device scratch (allocation-free rule: __device__ globals) ----
// f32 state: only x0, x1 are ever re-read in f32 (as 'prev' terms).
__device__ float    g_X0[V * FB];
__device__ float    g_X1[V * FB];
// fp16 mirrors, rho-major: row rho = v*2+b, 64 halves (f) per row = 32 uints.
__device__ unsigned g_H0[2 * V * 32];
__device__ unsigned g_H1[2 * V * 32];
__device__ unsigned g_H2[2 * V * 32];
__device__ unsigned g_H3[2 * V * 32];
__device__ unsigned g_Wh[KK * FIN * FOUT / 2];   // fp16 weights, 2 per uint
__device__ int      g_counts[V];     // zero-init; re-zeroed by scan_write
__device__ int      g_rowptr[V + 1];
__device__ int      g_cursor[V];
__device__ int      g_bsums[NB];
__device__ int2     g_edge[E];       // (col, float-bits of val)

__device__ __forceinline__ unsigned* hsel(int k) {
    switch (k) {
        case 0: return g_H0;
        case 1: return g_H1;
        case 2: return g_H2;
        default: return g_H3;
    }
}
__device__ __forceinline__ float* xfsel(int k) { return (k == 0) ? g_X0 : g_X1; }

// ---------------- 1) fused front: transpose + mirror0 + histogram + W->fp16 ---
#define TRANS_BLOCKS ((V * 32) / 256)        // 6250
#define HIST_BLOCKS  (E / 256)               // 3125
#define WCONV_BLOCKS ((KK * FIN * FOUT / 2) / 256)   // 32
__global__ void front_kernel(const float* __restrict__ in,
                             const float* __restrict__ wt,
                             const int* __restrict__ rows) {
    int blk = blockIdx.x;
    if (blk < TRANS_BLOCKS) {
        int idx = blk * 256 + threadIdx.x;   // over V*32 (f-pairs)
        int v = idx >> 5;
        int fp = idx & 31;                   // f0 = 2*fp
        float2 a = __ldg(&reinterpret_cast<const float2*>(in)[v * 32 + fp]);          // b=0
        float2 c = __ldg(&reinterpret_cast<const float2*>(in)[V * 32 + v * 32 + fp]); // b=1
        // f32 x0: [v][f*2+b]
        reinterpret_cast<float4*>(g_X0)[v * 32 + fp] = make_float4(a.x, c.x, a.y, c.y);
        // mirror rows: 2v (b=0), 2v+1 (b=1), halves (f0, f0+1)
        __half2 h0 = __floats2half2_rn(a.x, a.y);
        __half2 h1 = __floats2half2_rn(c.x, c.y);
        g_H0[(2 * v) * 32 + fp]     = *reinterpret_cast<unsigned*>(&h0);
        g_H0[(2 * v + 1) * 32 + fp] = *reinterpret_cast<unsigned*>(&h1);
    } else if (blk < TRANS_BLOCKS + HIST_BLOCKS) {
        int e = (blk - TRANS_BLOCKS) * 256 + threadIdx.x;
        atomicAdd(&g_counts[rows[e]], 1);
    } else {
        int i = (blk - TRANS_BLOCKS - HIST_BLOCKS) * 256 + threadIdx.x;  // over 8192
        __half2 h = __floats2half2_rn(wt[2 * i], wt[2 * i + 1]);
        g_Wh[i] = *reinterpret_cast<unsigned*>(&h);
    }
}

// ---------------- 2) CSR build ------------------------------------------------
__global__ void scan_reduce_kernel() {
    __shared__ int swarp[32];
    int tid = threadIdx.x;
    int i = blockIdx.x * 1024 + tid;
    int v = (i < V) ? g_counts[i] : 0;
    for (int o = 16; o > 0; o >>= 1) v += __shfl_down_sync(0xffffffffu, v, o);
    if ((tid & 31) == 0) swarp[tid >> 5] = v;
    __syncthreads();
    if (tid < 32) {
        int s = swarp[tid];
        for (int o = 16; o > 0; o >>= 1) s += __shfl_down_sync(0xffffffffu, s, o);
        if (tid == 0) g_bsums[blockIdx.x] = s;
    }
}

// per-block scan + write; inlines the 49-element bsums exclusive scan;
// re-zeros g_counts for the next graph replay.
__global__ void scan_write_kernel() {
    __shared__ int s[1024];
    __shared__ int boff;
    int tid = threadIdx.x;
    if (tid == 0) {
        int run = 0;
        for (int j = 0; j < NB; j++) {
            if (j == (int)blockIdx.x) boff = run;
            run += g_bsums[j];
        }
        if (blockIdx.x == 0) g_rowptr[V] = run;   // == E
    }
    int i = blockIdx.x * 1024 + tid;
    int v = (i < V) ? g_counts[i] : 0;
    s[tid] = v;
    __syncthreads();
#pragma unroll
    for (int o = 1; o < 1024; o <<= 1) {
        int t = (tid >= o) ? s[tid - o] : 0;
        __syncthreads();
        s[tid] += t;
        __syncthreads();
    }
    if (i < V) {
        int excl = s[tid] - v + boff;
        g_rowptr[i] = excl;
        g_cursor[i] = excl;
        g_counts[i] = 0;
    }
}

__global__ void scatter_kernel(const float* __restrict__ vals,
                               const int* __restrict__ rows,
                               const int* __restrict__ cols) {
    int e = blockIdx.x * blockDim.x + threadIdx.x;
    if (e >= E) return;
    int p = atomicAdd(&g_cursor[rows[e]], 1);
    g_edge[p] = make_int2(cols[e], __float_as_int(vals[e]));
}

// ---------------- 3) CSR SpMM -------------------------------------------------
// One warp per row; lane l owns f = 2l, 2l+1 for both b. Gathers the fp16
// mirror (two 128B rows per source vertex). Always writes the fp16 mirror of
// dst; writes f32 dst only if it is needed later as a 'prev' term.
__global__ void spmm_csr_kernel(int ksrc, int kdst, int kprev,
                                float alpha, float beta, int write_f32) {
    int gtid = blockIdx.x * blockDim.x + threadIdx.x;
    int r = gtid >> 5;
    int lane = gtid & 31;
    if (r >= V) return;

    const unsigned* __restrict__ hx = hsel(ksrc);
    int s = g_rowptr[r];
    int e = g_rowptr[r + 1];

    float4 acc0 = make_float4(0.f, 0.f, 0.f, 0.f);
    float4 acc1 = make_float4(0.f, 0.f, 0.f, 0.f);
    int i = s;
    for (; i + 1 < e; i += 2) {
        int2 e0 = __ldg(&g_edge[i]);
        int2 e1 = __ldg(&g_edge[i + 1]);
        float v0 = __int_as_float(e0.y);
        float v1 = __int_as_float(e1.y);
        unsigned ra0 = __ldg(&hx[(2 * e0.x) * 32 + lane]);       // b=0
        unsigned ra1 = __ldg(&hx[(2 * e0.x + 1) * 32 + lane]);   // b=1
        unsigned rb0 = __ldg(&hx[(2 * e1.x) * 32 + lane]);
        unsigned rb1 = __ldg(&hx[(2 * e1.x + 1) * 32 + lane]);
        float2 a0 = __half22float2(*reinterpret_cast<__half2*>(&ra0));
        float2 a1 = __half22float2(*reinterpret_cast<__half2*>(&ra1));
        float2 b0 = __half22float2(*reinterpret_cast<__half2*>(&rb0));
        float2 b1 = __half22float2(*reinterpret_cast<__half2*>(&rb1));
        acc0.x = fmaf(v0, a0.x, acc0.x);   // (f=2l,  b0)
        acc0.y = fmaf(v0, a1.x, acc0.y);   // (f=2l,  b1)
        acc0.z = fmaf(v0, a0.y, acc0.z);   // (f=2l+1,b0)
        acc0.w = fmaf(v0, a1.y, acc0.w);   // (f=2l+1,b1)
        acc1.x = fmaf(v1, b0.x, acc1.x);
        acc1.y = fmaf(v1, b1.x, acc1.y);
        acc1.z = fmaf(v1, b0.y, acc1.z);
        acc1.w = fmaf(v1, b1.y, acc1.w);
    }
    if (i < e) {
        int2 e0 = __ldg(&g_edge[i]);
        float v0 = __int_as_float(e0.y);
        unsigned ra0 = __ldg(&hx[(2 * e0.x) * 32 + lane]);
        unsigned ra1 = __ldg(&hx[(2 * e0.x + 1) * 32 + lane]);
        float2 a0 = __half22float2(*reinterpret_cast<__half2*>(&ra0));
        float2 a1 = __half22float2(*reinterpret_cast<__half2*>(&ra1));
        acc0.x = fmaf(v0, a0.x, acc0.x);
        acc0.y = fmaf(v0, a1.x, acc0.y);
        acc0.z = fmaf(v0, a0.y, acc0.z);
        acc0.w = fmaf(v0, a1.y, acc0.w);
    }
    acc0.x += acc1.x; acc0.y += acc1.y; acc0.z += acc1.z; acc0.w += acc1.w;

    float4 o;
    if (beta != 0.f) {
        float4 p = reinterpret_cast<const float4*>(xfsel(kprev))[r * 32 + lane];
        o.x = fmaf(beta, p.x, alpha * acc0.x);
        o.y = fmaf(beta, p.y, alpha * acc0.y);
        o.z = fmaf(beta, p.z, alpha * acc0.z);
        o.w = fmaf(beta, p.w, alpha * acc0.w);
    } else {
        o.x = alpha * acc0.x; o.y = alpha * acc0.y;
        o.z = alpha * acc0.z; o.w = alpha * acc0.w;
    }
    if (write_f32)
        reinterpret_cast<float4*>(xfsel(kdst))[r * 32 + lane] = o;

    // mirror: row 2r holds b=0 (o.x at f=2l, o.z at 2l+1); row 2r+1 holds b=1
    unsigned* hd = hsel(kdst);
    __half2 m0 = __floats2half2_rn(o.x, o.z);
    __half2 m1 = __floats2half2_rn(o.y, o.w);
    hd[(2 * r) * 32 + lane]     = *reinterpret_cast<unsigned*>(&m0);
    hd[(2 * r + 1) * 32 + lane] = *reinterpret_cast<unsigned*>(&m1);
}

// ---------------- 4) tensor-core GEMM ----------------------------------------
// out[b,v,o] = bias[o] + sum_{k,f} Hk[rho=v*2+b][f] * Wh[f*4+k][o], fp32 accum.
// Block: 128 rho-rows x 64 cols, 8 warps; warp w owns rows 16w..16w+15.
// Per k: stage A_k [128][64] fp16 (pad 72) + B_k [64][64] fp16, 4x wmma chunks.
#define AP 72   // padded half stride
__global__ void gemm_kernel(const float* __restrict__ bias,
                            float* __restrict__ out) {
    __shared__ __align__(16) char sbuf[35840];
    unsigned* As_u = reinterpret_cast<unsigned*>(sbuf);            // 128*36*4 = 18432B
    unsigned* Bs_u = reinterpret_cast<unsigned*>(sbuf + 18432);    //  64*36*4 =  9216B
    float*    Cs   = reinterpret_cast<float*>(sbuf);               // epilogue: 8*16*68*4

    int tid = threadIdx.x;
    int w = tid >> 5;
    int lane = tid & 31;
    int rho0 = blockIdx.x * 128;

    wmma::fragment<wmma::accumulator, 16, 16, 16, float> acc[4];
#pragma unroll
    for (int nt = 0; nt < 4; nt++) wmma::fill_fragment(acc[nt], 0.f);

    for (int k = 0; k < KK; k++) {
        __syncthreads();
        const unsigned* m = hsel(k);
#pragma unroll
        for (int it = 0; it < 16; it++) {        // A: 128 rows x 32 uints
            int i = tid + it * 256;
            int r = i >> 5, cu = i & 31;
            int rho = rho0 + r;
            As_u[r * 36 + cu] = (rho < 2 * V) ? __ldcg(&m[rho * 32 + cu]) : 0u;
        }
#pragma unroll
        for (int it = 0; it < 8; it++) {         // B: 64 rows x 32 uints
            int i = tid + it * 256;
            int f = i >> 5, cu = i & 31;
            Bs_u[f * 36 + cu] = __ldg(&g_Wh[(f * 4 + k) * 32 + cu]);
        }
        __syncthreads();

        const __half* As = reinterpret_cast<const __half*>(As_u);
        const __half* Bs = reinterpret_cast<const __half*>(Bs_u);
#pragma unroll
        for (int kc = 0; kc < 4; kc++) {
            wmma::fragment<wmma::matrix_a, 16, 16, 16, __half, wmma::row_major> af;
            wmma::load_matrix_sync(af, As + (w * 16) * AP + kc * 16, AP);
#pragma unroll
            for (int nt = 0; nt < 4; nt++) {
                wmma::fragment<wmma::matrix_b, 16, 16, 16, __half, wmma::row_major> bf;
                wmma::load_matrix_sync(bf, Bs + (kc * 16) * AP + nt * 16, AP);
                wmma::mma_sync(acc[nt], af, bf, acc[nt]);
            }
        }
    }

    __syncthreads();   // done with As/Bs; reuse sbuf as Cs
    float* Cw = Cs + w * 16 * 68;
#pragma unroll
    for (int nt = 0; nt < 4; nt++)
        wmma::store_matrix_sync(Cw + nt * 16, acc[nt], 68, wmma::mem_row_major);
    __syncwarp();

    const float4* b4 = reinterpret_cast<const float4*>(bias);
    float4* out4 = reinterpret_cast<float4*>(out);
#pragma unroll
    for (int j = 0; j < 8; j++) {
        int idx = lane + j * 32;            // 0..255 = 16 rows x 16 float4
        int r = idx >> 4, c4 = idx & 15;
        int rho = rho0 + w * 16 + r;
        if (rho < 2 * V) {
            int v = rho >> 1, b = rho & 1;
            float4 cv = *reinterpret_cast<const float4*>(&Cw[r * 68 + c4 * 4]);
            float4 bb = __ldg(&b4[c4]);
            out4[(b * V + v) * 16 + c4] =
                make_float4(cv.x + bb.x, cv.y + bb.y, cv.z + bb.z, cv.w + bb.w);
        }
    }
}

// ---------------- launch ------------------------------------------------------
extern "C" void kernel_launch(void* const* d_in, const int* in_sizes, int n_in,
                              void* d_out, int out_size) {
    const float* inputs   = (const float*)d_in[0];   // [B, V, FIN]
    const float* weight   = (const float*)d_in[1];   // [K, FIN, FOUT]
    const float* bias     = (const float*)d_in[2];   // [FOUT]
    const float* lap_vals = (const float*)d_in[3];   // [E]
    const int*   lap_rows = (const int*)d_in[4];     // [E]
    const int*   lap_cols = (const int*)d_in[5];     // [E]
    float*       out      = (float*)d_out;           // [B, V, FOUT]

    front_kernel<<<TRANS_BLOCKS + HIST_BLOCKS + WCONV_BLOCKS, 256>>>(inputs, weight, lap_rows);
    scan_reduce_kernel<<<NB, 1024>>>();
    scan_write_kernel<<<NB, 1024>>>();
    scatter_kernel<<<(E + 255) / 256, 256>>>(lap_vals, lap_rows, lap_cols);

    const int spmm_blocks = (V * 32 + 255) / 256;
    spmm_csr_kernel<<<spmm_blocks, 256>>>(0, 1, 0, 1.f, 0.f, 1);   // x1 = L x0        (f32+mirror)
    spmm_csr_kernel<<<spmm_blocks, 256>>>(1, 2, 0, 2.f, -1.f, 0);  // x2 = 2Lx1 - x0   (mirror only)
    spmm_csr_kernel<<<spmm_blocks, 256>>>(2, 3, 1, 2.f, -1.f, 0);  // x3 = 2Lx2 - x1   (mirror only)

    gemm_kernel<<<(2 * V + 127) / 128, 256>>>(bias, out);
}

// round 9
// speedup vs baseline: 2.1875x; 1.1049x over previous
#include <cuda_runtime.h>
#include <cuda_fp16.h>
#include <mma.h>

using namespace nvcuda;

#define V    50000
#define E    800000
#define BB   2
#define FIN  64
#define FOUT 64
#define KK   4
#define NB   ((V + 1023) / 1024)   // 49 scan blocks

// ---------------- device scratch (allocation-free rule: __device__ globals) ----
// fp16 state only. Layout per vertex v: 64 uints = 128 halves;
//   uint j in [0,32): b=0, features (2j, 2j+1)
//   uint j in [32,64): b=1, features (2(j-32), 2(j-32)+1)
__device__ unsigned g_H0[V * 64];
__device__ unsigned g_H1[V * 64];
__device__ unsigned g_H2[V * 64];
__device__ unsigned g_H3[V * 64];
__device__ unsigned g_Wh[KK * FIN * FOUT / 2];   // fp16 weights, 2 per uint
__device__ int      g_counts[V];     // zero-init; re-zeroed by scan_write
__device__ int      g_rowptr[V + 1];
__device__ int      g_cursor[V];
__device__ int      g_bsums[NB];
__device__ int2     g_edge[E];       // (col, float-bits of val)

__device__ __forceinline__ unsigned* hsel(int k) {
    switch (k) {
        case 0: return g_H0;
        case 1: return g_H1;
        case 2: return g_H2;
        default: return g_H3;
    }
}

// ---------------- 1) fused front: transpose+mirror + histogram + W->fp16 ------
#define TRANS_BLOCKS ((V * 32) / 256)        // 6250
#define HIST_BLOCKS  (E / 256)               // 3125
#define WCONV_BLOCKS ((KK * FIN * FOUT / 2) / 256)   // 32
__global__ void front_kernel(const float* __restrict__ in,
                             const float* __restrict__ wt,
                             const int* __restrict__ rows) {
    int blk = blockIdx.x;
    if (blk < TRANS_BLOCKS) {
        int idx = blk * 256 + threadIdx.x;   // over V*32 f-pairs
        int v = idx >> 5;
        int fp = idx & 31;                   // features (2fp, 2fp+1)
        float2 a = __ldg(&reinterpret_cast<const float2*>(in)[v * 32 + fp]);          // b=0
        float2 c = __ldg(&reinterpret_cast<const float2*>(in)[V * 32 + v * 32 + fp]); // b=1
        __half2 h0 = __floats2half2_rn(a.x, a.y);
        __half2 h1 = __floats2half2_rn(c.x, c.y);
        g_H0[v * 64 + fp]      = *reinterpret_cast<unsigned*>(&h0);
        g_H0[v * 64 + 32 + fp] = *reinterpret_cast<unsigned*>(&h1);
    } else if (blk < TRANS_BLOCKS + HIST_BLOCKS) {
        int e = (blk - TRANS_BLOCKS) * 256 + threadIdx.x;
        atomicAdd(&g_counts[rows[e]], 1);
    } else {
        int i = (blk - TRANS_BLOCKS - HIST_BLOCKS) * 256 + threadIdx.x;  // over 8192
        __half2 h = __floats2half2_rn(wt[2 * i], wt[2 * i + 1]);
        g_Wh[i] = *reinterpret_cast<unsigned*>(&h);
    }
}

// ---------------- 2) CSR build ------------------------------------------------
__global__ void scan_reduce_kernel() {
    __shared__ int swarp[32];
    int tid = threadIdx.x;
    int i = blockIdx.x * 1024 + tid;
    int v = (i < V) ? g_counts[i] : 0;
    for (int o = 16; o > 0; o >>= 1) v += __shfl_down_sync(0xffffffffu, v, o);
    if ((tid & 31) == 0) swarp[tid >> 5] = v;
    __syncthreads();
    if (tid < 32) {
        int s = swarp[tid];
        for (int o = 16; o > 0; o >>= 1) s += __shfl_down_sync(0xffffffffu, s, o);
        if (tid == 0) g_bsums[blockIdx.x] = s;
    }
}

__global__ void scan_write_kernel() {
    __shared__ int s[1024];
    __shared__ int boff;
    int tid = threadIdx.x;
    if (tid == 0) {
        int run = 0;
        for (int j = 0; j < NB; j++) {
            if (j == (int)blockIdx.x) boff = run;
            run += g_bsums[j];
        }
        if (blockIdx.x == 0) g_rowptr[V] = run;   // == E
    }
    int i = blockIdx.x * 1024 + tid;
    int v = (i < V) ? g_counts[i] : 0;
    s[tid] = v;
    __syncthreads();
#pragma unroll
    for (int o = 1; o < 1024; o <<= 1) {
        int t = (tid >= o) ? s[tid - o] : 0;
        __syncthreads();
        s[tid] += t;
        __syncthreads();
    }
    if (i < V) {
        int excl = s[tid] - v + boff;
        g_rowptr[i] = excl;
        g_cursor[i] = excl;
        g_counts[i] = 0;
    }
}

__global__ void scatter_kernel(const float* __restrict__ vals,
                               const int* __restrict__ rows,
                               const int* __restrict__ cols) {
    int e = blockIdx.x * blockDim.x + threadIdx.x;
    if (e >= E) return;
    int p = atomicAdd(&g_cursor[rows[e]], 1);
    g_edge[p] = make_int2(cols[e], __float_as_int(vals[e]));
}

// ---------------- 3) CSR SpMM (all-fp16 state, f32 math) ----------------------
// One warp per row. Lane l owns halves (4l..4l+3) of the 128-half vertex row:
// ONE LDG.64 per edge per lane (256B contiguous per edge). prev also fp16.
__global__ void spmm_csr_kernel(int ksrc, int kdst, int kprev,
                                float alpha, float beta) {
    int gtid = blockIdx.x * blockDim.x + threadIdx.x;
    int r = gtid >> 5;
    int lane = gtid & 31;
    if (r >= V) return;

    const uint2* __restrict__ hx = reinterpret_cast<const uint2*>(hsel(ksrc));
    int s = g_rowptr[r];
    int e = g_rowptr[r + 1];

    float4 acc0 = make_float4(0.f, 0.f, 0.f, 0.f);
    float4 acc1 = make_float4(0.f, 0.f, 0.f, 0.f);
    int i = s;
    for (; i + 1 < e; i += 2) {
        int2 e0 = __ldg(&g_edge[i]);
        int2 e1 = __ldg(&g_edge[i + 1]);
        float v0 = __int_as_float(e0.y);
        float v1 = __int_as_float(e1.y);
        uint2 ra = __ldg(&hx[e0.x * 32 + lane]);
        uint2 rb = __ldg(&hx[e1.x * 32 + lane]);
        float2 a0 = __half22float2(*reinterpret_cast<__half2*>(&ra.x));
        float2 a1 = __half22float2(*reinterpret_cast<__half2*>(&ra.y));
        float2 b0 = __half22float2(*reinterpret_cast<__half2*>(&rb.x));
        float2 b1 = __half22float2(*reinterpret_cast<__half2*>(&rb.y));
        acc0.x = fmaf(v0, a0.x, acc0.x);
        acc0.y = fmaf(v0, a0.y, acc0.y);
        acc0.z = fmaf(v0, a1.x, acc0.z);
        acc0.w = fmaf(v0, a1.y, acc0.w);
        acc1.x = fmaf(v1, b0.x, acc1.x);
        acc1.y = fmaf(v1, b0.y, acc1.y);
        acc1.z = fmaf(v1, b1.x, acc1.z);
        acc1.w = fmaf(v1, b1.y, acc1.w);
    }
    if (i < e) {
        int2 e0 = __ldg(&g_edge[i]);
        float v0 = __int_as_float(e0.y);
        uint2 ra = __ldg(&hx[e0.x * 32 + lane]);
        float2 a0 = __half22float2(*reinterpret_cast<__half2*>(&ra.x));
        float2 a1 = __half22float2(*reinterpret_cast<__half2*>(&ra.y));
        acc0.x = fmaf(v0, a0.x, acc0.x);
        acc0.y = fmaf(v0, a0.y, acc0.y);
        acc0.z = fmaf(v0, a1.x, acc0.z);
        acc0.w = fmaf(v0, a1.y, acc0.w);
    }
    acc0.x += acc1.x; acc0.y += acc1.y; acc0.z += acc1.z; acc0.w += acc1.w;

    float4 o;
    if (beta != 0.f) {
        uint2 rp = __ldg(&reinterpret_cast<const uint2*>(hsel(kprev))[r * 32 + lane]);
        float2 p0 = __half22float2(*reinterpret_cast<__half2*>(&rp.x));
        float2 p1 = __half22float2(*reinterpret_cast<__half2*>(&rp.y));
        o.x = fmaf(beta, p0.x, alpha * acc0.x);
        o.y = fmaf(beta, p0.y, alpha * acc0.y);
        o.z = fmaf(beta, p1.x, alpha * acc0.z);
        o.w = fmaf(beta, p1.y, alpha * acc0.w);
    } else {
        o.x = alpha * acc0.x; o.y = alpha * acc0.y;
        o.z = alpha * acc0.z; o.w = alpha * acc0.w;
    }

    uint2 m;
    __half2 m0 = __floats2half2_rn(o.x, o.y);
    __half2 m1 = __floats2half2_rn(o.z, o.w);
    m.x = *reinterpret_cast<unsigned*>(&m0);
    m.y = *reinterpret_cast<unsigned*>(&m1);
    reinterpret_cast<uint2*>(hsel(kdst))[r * 32 + lane] = m;
}

// ---------------- 4) tensor-core GEMM ----------------------------------------
// out[b,v,o] = bias[o] + sum_{k,f} Hk[v][b-half f] * Wh[f*4+k][o], fp32 accum.
#define AP 72   // padded half stride
__global__ void gemm_kernel(const float* __restrict__ bias,
                            float* __restrict__ out) {
    __shared__ __align__(16) char sbuf[35840];
    unsigned* As_u = reinterpret_cast<unsigned*>(sbuf);            // 128*36*4
    unsigned* Bs_u = reinterpret_cast<unsigned*>(sbuf + 18432);    //  64*36*4
    float*    Cs   = reinterpret_cast<float*>(sbuf);               // epilogue

    int tid = threadIdx.x;
    int w = tid >> 5;
    int lane = tid & 31;
    int rho0 = blockIdx.x * 128;

    wmma::fragment<wmma::accumulator, 16, 16, 16, float> acc[4];
#pragma unroll
    for (int nt = 0; nt < 4; nt++) wmma::fill_fragment(acc[nt], 0.f);

    for (int k = 0; k < KK; k++) {
        __syncthreads();
        const unsigned* m = hsel(k);
#pragma unroll
        for (int it = 0; it < 16; it++) {        // A: 128 rho-rows x 32 uints
            int i = tid + it * 256;
            int r = i >> 5, cu = i & 31;
            int rho = rho0 + r;
            unsigned val = 0u;
            if (rho < 2 * V)
                val = __ldcg(&m[(rho >> 1) * 64 + (rho & 1) * 32 + cu]);
            As_u[r * 36 + cu] = val;
        }
#pragma unroll
        for (int it = 0; it < 8; it++) {         // B: 64 f-rows x 32 uints
            int i = tid + it * 256;
            int f = i >> 5, cu = i & 31;
            Bs_u[f * 36 + cu] = __ldg(&g_Wh[(f * 4 + k) * 32 + cu]);
        }
        __syncthreads();

        const __half* As = reinterpret_cast<const __half*>(As_u);
        const __half* Bs = reinterpret_cast<const __half*>(Bs_u);
#pragma unroll
        for (int kc = 0; kc < 4; kc++) {
            wmma::fragment<wmma::matrix_a, 16, 16, 16, __half, wmma::row_major> af;
            wmma::load_matrix_sync(af, As + (w * 16) * AP + kc * 16, AP);
#pragma unroll
            for (int nt = 0; nt < 4; nt++) {
                wmma::fragment<wmma::matrix_b, 16, 16, 16, __half, wmma::row_major> bf;
                wmma::load_matrix_sync(bf, Bs + (kc * 16) * AP + nt * 16, AP);
                wmma::mma_sync(acc[nt], af, bf, acc[nt]);
            }
        }
    }

    __syncthreads();   // done with As/Bs; reuse sbuf as Cs
    float* Cw = Cs + w * 16 * 68;
#pragma unroll
    for (int nt = 0; nt < 4; nt++)
        wmma::store_matrix_sync(Cw + nt * 16, acc[nt], 68, wmma::mem_row_major);
    __syncwarp();

    const float4* b4 = reinterpret_cast<const float4*>(bias);
    float4* out4 = reinterpret_cast<float4*>(out);
#pragma unroll
    for (int j = 0; j < 8; j++) {
        int idx = lane + j * 32;            // 16 rows x 16 float4
        int r = idx >> 4, c4 = idx & 15;
        int rho = rho0 + w * 16 + r;
        if (rho < 2 * V) {
            int v = rho >> 1, b = rho & 1;
            float4 cv = *reinterpret_cast<const float4*>(&Cw[r * 68 + c4 * 4]);
            float4 bb = __ldg(&b4[c4]);
            out4[(b * V + v) * 16 + c4] =
                make_float4(cv.x + bb.x, cv.y + bb.y, cv.z + bb.z, cv.w + bb.w);
        }
    }
}

// ---------------- launch ------------------------------------------------------
extern "C" void kernel_launch(void* const* d_in, const int* in_sizes, int n_in,
                              void* d_out, int out_size) {
    const float* inputs   = (const float*)d_in[0];   // [B, V, FIN]
    const float* weight   = (const float*)d_in[1];   // [K, FIN, FOUT]
    const float* bias     = (const float*)d_in[2];   // [FOUT]
    const float* lap_vals = (const float*)d_in[3];   // [E]
    const int*   lap_rows = (const int*)d_in[4];     // [E]
    const int*   lap_cols = (const int*)d_in[5];     // [E]
    float*       out      = (float*)d_out;           // [B, V, FOUT]

    front_kernel<<<TRANS_BLOCKS + HIST_BLOCKS + WCONV_BLOCKS, 256>>>(inputs, weight, lap_rows);
    scan_reduce_kernel<<<NB, 1024>>>();
    scan_write_kernel<<<NB, 1024>>>();
    scatter_kernel<<<(E + 255) / 256, 256>>>(lap_vals, lap_rows, lap_cols);

    const int spmm_blocks = (V * 32 + 255) / 256;
    spmm_csr_kernel<<<spmm_blocks, 256>>>(0, 1, 0, 1.f, 0.f);    // x1 = L x0
    spmm_csr_kernel<<<spmm_blocks, 256>>>(1, 2, 0, 2.f, -1.f);   // x2 = 2Lx1 - x0
    spmm_csr_kernel<<<spmm_blocks, 256>>>(2, 3, 1, 2.f, -1.f);   // x3 = 2Lx2 - x1

    gemm_kernel<<<(2 * V + 127) / 128, 256>>>(bias, out);
}